// round 1
// baseline (speedup 1.0000x reference)
#include <cuda_runtime.h>
#include <cstdint>
#include <cstddef>

// Problem constants
#define Bsz 8
#define Hn  16
#define Nn  4096
#define DHn 64
#define Kn  128
#define Dn  1024

// Scratch for projected K/V: [b][k][d], 4 MB each (device globals: no allocs allowed)
__device__ float g_kp[Bsz * Kn * Dn];
__device__ float g_vp[Bsz * Kn * Dn];

typedef unsigned long long u64;

// Packed fp32x2 FMA (Blackwell): doubles fp32 MAC throughput vs FFMA-3reg.
__device__ __forceinline__ void fma2(u64& acc, u64 a, u64 b) {
    asm("fma.rn.f32x2 %0, %1, %2, %0;" : "+l"(acc) : "l"(a), "l"(b));
}
__device__ __forceinline__ u64 pack2(float x, float y) {
    u64 r; asm("mov.b64 %0, {%1, %2};" : "=l"(r) : "f"(x), "f"(y)); return r;
}
__device__ __forceinline__ void unpack2(u64 v, float& x, float& y) {
    asm("mov.b64 {%0, %1}, %2;" : "=f"(x), "=f"(y) : "l"(v));
}

// ============================================================================
// Stage 1: projections.  C[k, d] = sum_n P[n,k] * X[b,n,d]
// Grid: (dtile 0..7, b 0..7, which 0..1).  CTA tile: 128k x 128d, loop n.
// Thread tile: 4 k-pairs (8 k) x 8 d  ->  32 FFMA2 per inner step.
// ============================================================================
__global__ void __launch_bounds__(256, 1) proj_kernel(
    const float* __restrict__ keys, const float* __restrict__ values,
    const float* __restrict__ pk,   const float* __restrict__ pv)
{
    const int dt = blockIdx.x;
    const int b  = blockIdx.y;
    const int w  = blockIdx.z;

    const float* __restrict__ X = (w ? values : keys) + (size_t)b * Nn * Dn + dt * 128;
    const float* __restrict__ P = (w ? pv : pk);
    float* __restrict__ C = (w ? g_vp : g_kp) + (size_t)b * Kn * Dn + dt * 128;

    __shared__ __align__(16) float sP[32][132];   // P chunk [nn][k]
    __shared__ __align__(16) float sX[32][132];   // X chunk [nn][d]

    const int tid = threadIdx.x;
    const int ty = tid >> 4;    // 0..15
    const int tx = tid & 15;    // 0..15

    u64 acc[4][8];
    #pragma unroll
    for (int i = 0; i < 4; i++)
        #pragma unroll
        for (int j = 0; j < 8; j++) acc[i][j] = 0ull;

    float4 rP[4], rX[4];

    // prefetch chunk 0 into registers
    #pragma unroll
    for (int t = 0; t < 4; t++) {
        int idx = tid + 256 * t;
        int row = idx >> 5;           // 0..31
        int c   = (idx & 31) * 4;     // 0..124
        rP[t] = *(const float4*)&P[(size_t)row * Kn + c];
        rX[t] = *(const float4*)&X[(size_t)row * Dn + c];
    }

    for (int n0 = 0; n0 < Nn; n0 += 32) {
        // registers -> smem
        #pragma unroll
        for (int t = 0; t < 4; t++) {
            int idx = tid + 256 * t;
            int row = idx >> 5;
            int c   = (idx & 31) * 4;
            *(float4*)&sP[row][c] = rP[t];
            *(float4*)&sX[row][c] = rX[t];
        }
        __syncthreads();

        // prefetch next chunk (overlaps with compute below)
        if (n0 + 32 < Nn) {
            #pragma unroll
            for (int t = 0; t < 4; t++) {
                int idx = tid + 256 * t;
                int row = idx >> 5;
                int c   = (idx & 31) * 4;
                rP[t] = *(const float4*)&P[(size_t)(n0 + 32 + row) * Kn + c];
                rX[t] = *(const float4*)&X[(size_t)(n0 + 32 + row) * Dn + c];
            }
        }

        // compute on current chunk
        #pragma unroll 4
        for (int nn = 0; nn < 32; nn++) {
            u64 a[4];
            #pragma unroll
            for (int i = 0; i < 4; i++)
                a[i] = *(const u64*)&sP[nn][ty * 2 + 32 * i];   // (P[n,k], P[n,k+1])
            u64 bb[8];
            #pragma unroll
            for (int j = 0; j < 8; j++) {
                float s = sX[nn][tx + 16 * j];
                bb[j] = pack2(s, s);
            }
            #pragma unroll
            for (int i = 0; i < 4; i++)
                #pragma unroll
                for (int j = 0; j < 8; j++) fma2(acc[i][j], a[i], bb[j]);
        }
        __syncthreads();
    }

    // epilogue
    #pragma unroll
    for (int i = 0; i < 4; i++) {
        int k = ty * 2 + 32 * i;
        #pragma unroll
        for (int j = 0; j < 8; j++) {
            float c0, c1;
            unpack2(acc[i][j], c0, c1);
            C[(size_t)k * Dn + tx + 16 * j]       = c0;
            C[(size_t)(k + 1) * Dn + tx + 16 * j] = c1;
        }
    }
}

// ============================================================================
// Stage 2: fused attention per (b, h, 128-row n-tile).
//   dots = (Q*scale) . KK^T  (inner 64)  -> softmax over k=128 -> out = P . VV
// smem: qT[64][130] (dh-major transposed, scale folded), kT[64][130],
//       pT[128][130] (k-major dots), vv[128][64], rinv[128].  ~166 KB.
// ============================================================================
#define SM_QT 0
#define SM_KT 8320
#define SM_PT 16640
#define SM_VV 33280
#define SM_RI 41472
#define SM_FLOATS 41600
#define SMEM2_BYTES (SM_FLOATS * 4)

__global__ void __launch_bounds__(256, 1) attn_kernel(
    const float* __restrict__ qg, float* __restrict__ outg)
{
    const int nt = blockIdx.x;   // 0..31
    const int h  = blockIdx.y;   // 0..15
    const int b  = blockIdx.z;   // 0..7

    extern __shared__ __align__(16) float sm[];
    float* qT   = sm + SM_QT;    // qT[dh*130 + r]
    float* kT   = sm + SM_KT;    // kT[dh*130 + k]
    float* pT   = sm + SM_PT;    // pT[k*130 + r]
    float* vv   = sm + SM_VV;    // vv[k*64 + dh]
    float* rinv = sm + SM_RI;

    const int tid = threadIdx.x;
    const int ty = tid >> 4;
    const int tx = tid & 15;

    // ---- load Q tile (transposed, scaled), KK (transposed), VV ----
    {
        const size_t qbase = ((size_t)b * Nn + (size_t)nt * 128) * Dn + h * 64;
        const size_t kbase = (size_t)b * Kn * Dn + h * 64;
        #pragma unroll
        for (int t = 0; t < 8; t++) {
            int idx = tid + 256 * t;
            int r  = idx >> 4;          // 0..127  (row n or k)
            int c4 = (idx & 15) * 4;    // 0..60
            float4 v = *(const float4*)&qg[qbase + (size_t)r * Dn + c4];
            qT[(c4 + 0) * 130 + r] = v.x * 0.125f;
            qT[(c4 + 1) * 130 + r] = v.y * 0.125f;
            qT[(c4 + 2) * 130 + r] = v.z * 0.125f;
            qT[(c4 + 3) * 130 + r] = v.w * 0.125f;
            float4 kv = *(const float4*)&g_kp[kbase + (size_t)r * Dn + c4];
            kT[(c4 + 0) * 130 + r] = kv.x;
            kT[(c4 + 1) * 130 + r] = kv.y;
            kT[(c4 + 2) * 130 + r] = kv.z;
            kT[(c4 + 3) * 130 + r] = kv.w;
            float4 vx = *(const float4*)&g_vp[kbase + (size_t)r * Dn + c4];
            *(float4*)&vv[r * 64 + c4] = vx;
        }
    }
    __syncthreads();

    // ---- GEMM1: dots[r, k], thread tile 4 r-pairs (8 r) x 8 k ----
    {
        u64 acc[4][8];
        #pragma unroll
        for (int i = 0; i < 4; i++)
            #pragma unroll
            for (int j = 0; j < 8; j++) acc[i][j] = 0ull;

        #pragma unroll 2
        for (int dh = 0; dh < 64; dh++) {
            u64 a[4];
            #pragma unroll
            for (int i = 0; i < 4; i++)
                a[i] = *(const u64*)&qT[dh * 130 + ty * 2 + 32 * i];  // (q[r], q[r+1])
            u64 bb[8];
            #pragma unroll
            for (int j = 0; j < 8; j++) {
                float s = kT[dh * 130 + tx + 16 * j];
                bb[j] = pack2(s, s);
            }
            #pragma unroll
            for (int i = 0; i < 4; i++)
                #pragma unroll
                for (int j = 0; j < 8; j++) fma2(acc[i][j], a[i], bb[j]);
        }
        // store dots k-major: pT[k][r], r-pair contiguous
        #pragma unroll
        for (int i = 0; i < 4; i++)
            #pragma unroll
            for (int j = 0; j < 8; j++)
                *(u64*)&pT[(tx + 16 * j) * 130 + ty * 2 + 32 * i] = acc[i][j];
    }
    __syncthreads();

    // ---- softmax over k (warp per row, 16 rows per warp) ----
    {
        const int wid = tid >> 5, lane = tid & 31;
        for (int rr = 0; rr < 16; rr++) {
            int row = wid * 16 + rr;
            float x0 = pT[(lane      ) * 130 + row];
            float x1 = pT[(lane + 32 ) * 130 + row];
            float x2 = pT[(lane + 64 ) * 130 + row];
            float x3 = pT[(lane + 96 ) * 130 + row];
            float m = fmaxf(fmaxf(x0, x1), fmaxf(x2, x3));
            #pragma unroll
            for (int o = 16; o > 0; o >>= 1)
                m = fmaxf(m, __shfl_xor_sync(0xffffffffu, m, o));
            x0 = __expf(x0 - m); x1 = __expf(x1 - m);
            x2 = __expf(x2 - m); x3 = __expf(x3 - m);
            float s = (x0 + x1) + (x2 + x3);
            #pragma unroll
            for (int o = 16; o > 0; o >>= 1)
                s += __shfl_xor_sync(0xffffffffu, s, o);
            pT[(lane      ) * 130 + row] = x0;
            pT[(lane + 32 ) * 130 + row] = x1;
            pT[(lane + 64 ) * 130 + row] = x2;
            pT[(lane + 96 ) * 130 + row] = x3;
            if (lane == 0) rinv[row] = 1.0f / s;
        }
    }
    __syncthreads();

    // ---- GEMM2: out[r, dh] = sum_k p[k][r] * vv[k][dh]; 8 r x 2 dh-pairs ----
    {
        u64 o2[8][2];
        #pragma unroll
        for (int i = 0; i < 8; i++) { o2[i][0] = 0ull; o2[i][1] = 0ull; }

        #pragma unroll 4
        for (int k = 0; k < 128; k++) {
            u64 ap[8];
            #pragma unroll
            for (int i = 0; i < 8; i++) {
                float p = pT[k * 130 + ty + 16 * i];
                ap[i] = pack2(p, p);
            }
            u64 bv0 = *(const u64*)&vv[k * 64 + tx * 4];
            u64 bv1 = *(const u64*)&vv[k * 64 + tx * 4 + 2];
            #pragma unroll
            for (int i = 0; i < 8; i++) {
                fma2(o2[i][0], ap[i], bv0);
                fma2(o2[i][1], ap[i], bv1);
            }
        }

        const size_t obase = ((size_t)b * Nn + (size_t)nt * 128) * Dn + h * 64 + tx * 4;
        #pragma unroll
        for (int i = 0; i < 8; i++) {
            int r = ty + 16 * i;
            float ri = rinv[r];
            float f0, f1, f2, f3;
            unpack2(o2[i][0], f0, f1);
            unpack2(o2[i][1], f2, f3);
            float4 v;
            v.x = f0 * ri; v.y = f1 * ri; v.z = f2 * ri; v.w = f3 * ri;
            *(float4*)&outg[obase + (size_t)r * Dn] = v;
        }
    }
}

// ============================================================================
// Launch
// ============================================================================
extern "C" void kernel_launch(void* const* d_in, const int* in_sizes, int n_in,
                              void* d_out, int out_size)
{
    const float* q      = (const float*)d_in[0];
    const float* keys   = (const float*)d_in[1];
    const float* values = (const float*)d_in[2];
    const float* pk     = (const float*)d_in[3];
    const float* pv     = (const float*)d_in[4];
    float* out = (float*)d_out;

    cudaFuncSetAttribute(attn_kernel,
                         cudaFuncAttributeMaxDynamicSharedMemorySize, SMEM2_BYTES);

    proj_kernel<<<dim3(8, 8, 2), 256>>>(keys, values, pk, pv);
    attn_kernel<<<dim3(Nn / 128, Hn, Bsz), 256, SMEM2_BYTES>>>(q, out);
}

// round 4
// speedup vs baseline: 1.3282x; 1.3282x over previous
#include <cuda_runtime.h>
#include <cstdint>
#include <cstddef>

// Problem constants
#define Bsz 8
#define Hn  16
#define Nn  4096
#define DHn 64
#define Kn  128
#define Dn  1024

// Device scratch (no allocs allowed)
__device__ float    g_kp[Bsz * Kn * Dn];           // 4 MB projected keys
__device__ float    g_vp[Bsz * Kn * Dn];           // 4 MB projected values
__device__ uint32_t g_PTh[2 * Kn * (Nn / 2)];      // P^T hi bf16 pairs [w][k][n/2]
__device__ uint32_t g_PTl[2 * Kn * (Nn / 2)];      // P^T lo bf16 pairs

typedef unsigned long long u64;

// ---------------------------------------------------------------------------
// helpers
// ---------------------------------------------------------------------------
// pack two f32 -> bf16x2 (hi_elem -> upper 16 bits, lo_elem -> lower 16 bits)
__device__ __forceinline__ uint32_t cvt2bf(float hi_elem, float lo_elem) {
    uint32_t r;
    asm("cvt.rn.bf16x2.f32 %0, %1, %2;" : "=r"(r) : "f"(hi_elem), "f"(lo_elem));
    return r;
}
__device__ __forceinline__ float bflo_f(uint32_t p) { return __uint_as_float(p << 16); }
__device__ __forceinline__ float bfhi_f(uint32_t p) { return __uint_as_float(p & 0xffff0000u); }

// swizzles: XOR 16B-unit index bits with low row bits (row stride 128B / 256B)
#define SWZ128(x) ((x) ^ (((x) >> 3) & 0x70))
#define SWZ256(x) ((x) ^ (((x) >> 4) & 0x70))

#define LDSM4(r, a) \
    asm volatile("ldmatrix.sync.aligned.m8n8.x4.shared.b16 {%0,%1,%2,%3}, [%4];" \
        : "=r"((r)[0]), "=r"((r)[1]), "=r"((r)[2]), "=r"((r)[3]) : "r"(a))
#define LDSM4T(r, a) \
    asm volatile("ldmatrix.sync.aligned.m8n8.x4.trans.shared.b16 {%0,%1,%2,%3}, [%4];" \
        : "=r"((r)[0]), "=r"((r)[1]), "=r"((r)[2]), "=r"((r)[3]) : "r"(a))
#define MMA_BF16(c, a, b0v, b1v) \
    asm volatile("mma.sync.aligned.m16n8k16.row.col.f32.bf16.bf16.f32 " \
        "{%0,%1,%2,%3}, {%4,%5,%6,%7}, {%8,%9}, {%0,%1,%2,%3};" \
        : "+f"((c)[0]), "+f"((c)[1]), "+f"((c)[2]), "+f"((c)[3]) \
        : "r"((a)[0]), "r"((a)[1]), "r"((a)[2]), "r"((a)[3]), "r"(b0v), "r"(b1v))

// fp32x2 helpers (attention kernel)
__device__ __forceinline__ void fma2(u64& acc, u64 a, u64 b) {
    asm("fma.rn.f32x2 %0, %1, %2, %0;" : "+l"(acc) : "l"(a), "l"(b));
}
__device__ __forceinline__ u64 pack2(float x, float y) {
    u64 r; asm("mov.b64 %0, {%1, %2};" : "=l"(r) : "f"(x), "f"(y)); return r;
}
__device__ __forceinline__ void unpack2(u64 v, float& x, float& y) {
    asm("mov.b64 {%0, %1}, %2;" : "=f"(x), "=f"(y) : "l"(v));
}
__device__ __forceinline__ uint32_t smem_u32(const void* p) {
    uint32_t a;
    asm("{ .reg .u64 t; cvta.to.shared.u64 t, %1; cvt.u32.u64 %0, t; }" : "=r"(a) : "l"(p));
    return a;
}

// ============================================================================
// Kernel 0: transpose P [4096 n][128 k] -> split-bf16 PT [w][128 k][4096 n]
// ============================================================================
__global__ void __launch_bounds__(256) ptrans_kernel(
    const float* __restrict__ pk, const float* __restrict__ pv)
{
    __shared__ float sT[128][33];
    const int t  = threadIdx.x;
    const int n0 = blockIdx.x * 32;
    const int w  = blockIdx.y;
    const float* __restrict__ P = w ? pv : pk;

    #pragma unroll
    for (int i = 0; i < 16; i++) {
        int idx = t + 256 * i;
        int r = idx >> 7, c = idx & 127;
        sT[c][r] = P[(size_t)(n0 + r) * Kn + c];
    }
    __syncthreads();

    uint32_t* __restrict__ oh = g_PTh + (size_t)w * Kn * (Nn / 2);
    uint32_t* __restrict__ ol = g_PTl + (size_t)w * Kn * (Nn / 2);
    #pragma unroll
    for (int i = 0; i < 8; i++) {
        int idx = t + 256 * i;
        int k = idx >> 4, pr = idx & 15;
        float x0 = sT[k][2 * pr], x1 = sT[k][2 * pr + 1];
        uint32_t h = cvt2bf(x1, x0);            // lo16 = x0 (n even), hi16 = x1
        float h0 = bflo_f(h), h1 = bfhi_f(h);
        uint32_t l = cvt2bf(x1 - h1, x0 - h0);
        size_t o = (size_t)k * (Nn / 2) + (n0 >> 1) + pr;
        oh[o] = h;
        ol[o] = l;
    }
}

// ============================================================================
// Kernel 1: mma.sync bf16-split projection.
//   C[k=128, d=128-slice] = sum_n PT[k][n] * X[n][d],  3-pass split bf16.
// Grid (dt=8, b=8, w=2) = 128 CTAs; 512 threads (16 warps: 4 m x 4 d).
// smem per stage: A(hi,lo) 128k x 64n bf16 (128B rows, SWZ128) = 2 x 16KB,
//                 B(hi,lo)  64n x 128d bf16 (256B rows, SWZ256) = 2 x 16KB.
// ============================================================================
#define PJ_AHI 0
#define PJ_ALO 16384
#define PJ_BHI 32768
#define PJ_BLO 49152
#define PJ_STAGE 65536
#define PJ_SMEM (2 * PJ_STAGE)

__global__ void __launch_bounds__(512, 1) proj_mma_kernel(
    const float* __restrict__ keys, const float* __restrict__ values)
{
    const int dt = blockIdx.x;    // 0..7
    const int b  = blockIdx.y;    // 0..7
    const int w  = blockIdx.z;    // 0..1

    const float* __restrict__ X = (w ? values : keys) + (size_t)b * Nn * Dn + dt * 128;
    const uint32_t* __restrict__ PTh = g_PTh + (size_t)w * Kn * (Nn / 2);
    const uint32_t* __restrict__ PTl = g_PTl + (size_t)w * Kn * (Nn / 2);
    float* __restrict__ Cg = (w ? g_vp : g_kp) + (size_t)b * Kn * Dn + dt * 128;

    extern __shared__ __align__(1024) unsigned char dsm[];
    const uint32_t sbase = smem_u32(dsm);

    const int tid  = threadIdx.x;
    const int wid  = tid >> 5, lane = tid & 31;
    const int warp_m = (wid >> 2) * 32;   // k-row base of this warp
    const int warp_d = (wid & 3) * 32;    // d base of this warp

    float acc[2][4][4];
    #pragma unroll
    for (int i = 0; i < 2; i++)
        #pragma unroll
        for (int j = 0; j < 4; j++)
            #pragma unroll
            for (int q = 0; q < 4; q++) acc[i][j][q] = 0.0f;

    uint4  pA[4];   // [0..1]=hi chunks, [2..3]=lo chunks
    float4 pB[4];

    // prefetch chunk 0
    #pragma unroll
    for (int u = 0; u < 2; u++) {
        int idx = tid + 512 * u;
        int row = idx >> 3, c8 = idx & 7;            // row=k 0..127, c8: 16B unit
        size_t o = (size_t)row * (Nn / 2) + c8 * 4;  // 4 uint32 pairs = 8 n
        pA[u]     = *(const uint4*)&PTh[o];
        pA[2 + u] = *(const uint4*)&PTl[o];
    }
    #pragma unroll
    for (int u = 0; u < 4; u++) {
        int idx = tid + 512 * u;
        int row = idx >> 5, c4 = idx & 31;           // row=n 0..63, d=c4*4
        pB[u] = *(const float4*)&X[(size_t)row * Dn + c4 * 4];
    }

    for (int c = 0; c < 64; ++c) {
        unsigned char* st = dsm + (c & 1) * PJ_STAGE;

        // ---- STS A (pre-split bf16, direct 16B copies) ----
        #pragma unroll
        for (int u = 0; u < 2; u++) {
            int idx = tid + 512 * u;
            int row = idx >> 3, c8 = idx & 7;
            uint32_t off = SWZ128((uint32_t)(row * 128 + c8 * 16));
            *(uint4*)(st + PJ_AHI + off) = pA[u];
            *(uint4*)(st + PJ_ALO + off) = pA[2 + u];
        }
        // ---- STS B with inline bf16 split (4 floats -> 8B hi + 8B lo) ----
        #pragma unroll
        for (int u = 0; u < 4; u++) {
            int idx = tid + 512 * u;
            int row = idx >> 5, c4 = idx & 31;
            float4 v = pB[u];
            uint32_t h01 = cvt2bf(v.y, v.x);
            uint32_t h23 = cvt2bf(v.w, v.z);
            float h0 = bflo_f(h01), h1 = bfhi_f(h01);
            float h2 = bflo_f(h23), h3 = bfhi_f(h23);
            uint32_t l01 = cvt2bf(v.y - h1, v.x - h0);
            uint32_t l23 = cvt2bf(v.w - h3, v.z - h2);
            uint32_t off = SWZ256((uint32_t)(row * 256 + c4 * 8));
            *(uint2*)(st + PJ_BHI + off) = make_uint2(h01, h23);
            *(uint2*)(st + PJ_BLO + off) = make_uint2(l01, l23);
        }
        __syncthreads();

        // ---- prefetch chunk c+1 (overlaps with MMA below) ----
        if (c < 63) {
            int nb = (c + 1) * 64;
            #pragma unroll
            for (int u = 0; u < 2; u++) {
                int idx = tid + 512 * u;
                int row = idx >> 3, c8 = idx & 7;
                size_t o = (size_t)row * (Nn / 2) + (nb >> 1) + c8 * 4;
                pA[u]     = *(const uint4*)&PTh[o];
                pA[2 + u] = *(const uint4*)&PTl[o];
            }
            #pragma unroll
            for (int u = 0; u < 4; u++) {
                int idx = tid + 512 * u;
                int row = idx >> 5, c4 = idx & 31;
                pB[u] = *(const float4*)&X[(size_t)(nb + row) * Dn + c4 * 4];
            }
        }

        // ---- compute: 4 k16-steps over the 64-n chunk ----
        const uint32_t sA = sbase + (c & 1) * PJ_STAGE;
        const uint32_t sB = sA + PJ_BHI;
        #pragma unroll
        for (int ks = 0; ks < 4; ks++) {
            uint32_t ah[2][4], al[2][4];
            #pragma unroll
            for (int mi = 0; mi < 2; mi++) {
                uint32_t off = SWZ128((uint32_t)((warp_m + mi * 16 + (lane & 15)) * 128
                                                 + ks * 32 + (lane >> 4) * 16));
                LDSM4(ah[mi], sA + PJ_AHI + off);
                LDSM4(al[mi], sA + PJ_ALO + off);
            }
            #pragma unroll
            for (int g2 = 0; g2 < 2; g2++) {
                uint32_t offb = SWZ256((uint32_t)((ks * 16 + (lane & 15)) * 256
                                                  + warp_d * 2 + g2 * 32 + (lane >> 4) * 16));
                uint32_t bh[4], bl[4];
                LDSM4T(bh, sB + offb);
                LDSM4T(bl, sB + (PJ_BLO - PJ_BHI) + offb);
                #pragma unroll
                for (int mi = 0; mi < 2; mi++) {
                    #pragma unroll
                    for (int jj = 0; jj < 2; jj++) {
                        float* cc = acc[mi][g2 * 2 + jj];
                        MMA_BF16(cc, ah[mi], bh[jj * 2], bh[jj * 2 + 1]);
                        MMA_BF16(cc, ah[mi], bl[jj * 2], bl[jj * 2 + 1]);
                        MMA_BF16(cc, al[mi], bh[jj * 2], bh[jj * 2 + 1]);
                    }
                }
            }
        }
        __syncthreads();
    }

    // ---- epilogue: direct STG (float2 per fragment row) ----
    #pragma unroll
    for (int mi = 0; mi < 2; mi++) {
        #pragma unroll
        for (int j = 0; j < 4; j++) {
            int row = warp_m + mi * 16 + (lane >> 2);
            int col = warp_d + j * 8 + (lane & 3) * 2;
            *(float2*)&Cg[(size_t)row * Dn + col] =
                make_float2(acc[mi][j][0], acc[mi][j][1]);
            *(float2*)&Cg[(size_t)(row + 8) * Dn + col] =
                make_float2(acc[mi][j][2], acc[mi][j][3]);
        }
    }
}

// ============================================================================
// Kernel 2: fused attention (identical to round-1 passing version)
// ============================================================================
#define SM_QT 0
#define SM_KT 8320
#define SM_PT 16640
#define SM_VV 33280
#define SM_RI 41472
#define SM_FLOATS 41600
#define SMEM2_BYTES (SM_FLOATS * 4)

__global__ void __launch_bounds__(256, 1) attn_kernel(
    const float* __restrict__ qg, float* __restrict__ outg)
{
    const int nt = blockIdx.x;
    const int h  = blockIdx.y;
    const int b  = blockIdx.z;

    extern __shared__ __align__(16) float sm[];
    float* qT   = sm + SM_QT;
    float* kT   = sm + SM_KT;
    float* pT   = sm + SM_PT;
    float* vv   = sm + SM_VV;
    float* rinv = sm + SM_RI;

    const int tid = threadIdx.x;
    const int ty = tid >> 4;
    const int tx = tid & 15;

    {
        const size_t qbase = ((size_t)b * Nn + (size_t)nt * 128) * Dn + h * 64;
        const size_t kbase = (size_t)b * Kn * Dn + h * 64;
        #pragma unroll
        for (int t = 0; t < 8; t++) {
            int idx = tid + 256 * t;
            int r  = idx >> 4;
            int c4 = (idx & 15) * 4;
            float4 v = *(const float4*)&qg[qbase + (size_t)r * Dn + c4];
            qT[(c4 + 0) * 130 + r] = v.x * 0.125f;
            qT[(c4 + 1) * 130 + r] = v.y * 0.125f;
            qT[(c4 + 2) * 130 + r] = v.z * 0.125f;
            qT[(c4 + 3) * 130 + r] = v.w * 0.125f;
            float4 kv = *(const float4*)&g_kp[kbase + (size_t)r * Dn + c4];
            kT[(c4 + 0) * 130 + r] = kv.x;
            kT[(c4 + 1) * 130 + r] = kv.y;
            kT[(c4 + 2) * 130 + r] = kv.z;
            kT[(c4 + 3) * 130 + r] = kv.w;
            float4 vx = *(const float4*)&g_vp[kbase + (size_t)r * Dn + c4];
            *(float4*)&vv[r * 64 + c4] = vx;
        }
    }
    __syncthreads();

    {
        u64 acc[4][8];
        #pragma unroll
        for (int i = 0; i < 4; i++)
            #pragma unroll
            for (int j = 0; j < 8; j++) acc[i][j] = 0ull;

        #pragma unroll 2
        for (int dh = 0; dh < 64; dh++) {
            u64 a[4];
            #pragma unroll
            for (int i = 0; i < 4; i++)
                a[i] = *(const u64*)&qT[dh * 130 + ty * 2 + 32 * i];
            u64 bb[8];
            #pragma unroll
            for (int j = 0; j < 8; j++) {
                float s = kT[dh * 130 + tx + 16 * j];
                bb[j] = pack2(s, s);
            }
            #pragma unroll
            for (int i = 0; i < 4; i++)
                #pragma unroll
                for (int j = 0; j < 8; j++) fma2(acc[i][j], a[i], bb[j]);
        }
        #pragma unroll
        for (int i = 0; i < 4; i++)
            #pragma unroll
            for (int j = 0; j < 8; j++)
                *(u64*)&pT[(tx + 16 * j) * 130 + ty * 2 + 32 * i] = acc[i][j];
    }
    __syncthreads();

    {
        const int wd = tid >> 5, lane = tid & 31;
        for (int rr = 0; rr < 16; rr++) {
            int row = wd * 16 + rr;
            float x0 = pT[(lane      ) * 130 + row];
            float x1 = pT[(lane + 32 ) * 130 + row];
            float x2 = pT[(lane + 64 ) * 130 + row];
            float x3 = pT[(lane + 96 ) * 130 + row];
            float m = fmaxf(fmaxf(x0, x1), fmaxf(x2, x3));
            #pragma unroll
            for (int o = 16; o > 0; o >>= 1)
                m = fmaxf(m, __shfl_xor_sync(0xffffffffu, m, o));
            x0 = __expf(x0 - m); x1 = __expf(x1 - m);
            x2 = __expf(x2 - m); x3 = __expf(x3 - m);
            float s = (x0 + x1) + (x2 + x3);
            #pragma unroll
            for (int o = 16; o > 0; o >>= 1)
                s += __shfl_xor_sync(0xffffffffu, s, o);
            pT[(lane      ) * 130 + row] = x0;
            pT[(lane + 32 ) * 130 + row] = x1;
            pT[(lane + 64 ) * 130 + row] = x2;
            pT[(lane + 96 ) * 130 + row] = x3;
            if (lane == 0) rinv[row] = 1.0f / s;
        }
    }
    __syncthreads();

    {
        u64 o2[8][2];
        #pragma unroll
        for (int i = 0; i < 8; i++) { o2[i][0] = 0ull; o2[i][1] = 0ull; }

        #pragma unroll 4
        for (int k = 0; k < 128; k++) {
            u64 ap[8];
            #pragma unroll
            for (int i = 0; i < 8; i++) {
                float p = pT[k * 130 + ty + 16 * i];
                ap[i] = pack2(p, p);
            }
            u64 bv0 = *(const u64*)&vv[k * 64 + tx * 4];
            u64 bv1 = *(const u64*)&vv[k * 64 + tx * 4 + 2];
            #pragma unroll
            for (int i = 0; i < 8; i++) {
                fma2(o2[i][0], ap[i], bv0);
                fma2(o2[i][1], ap[i], bv1);
            }
        }

        const size_t obase = ((size_t)b * Nn + (size_t)nt * 128) * Dn + h * 64 + tx * 4;
        #pragma unroll
        for (int i = 0; i < 8; i++) {
            int r = ty + 16 * i;
            float ri = rinv[r];
            float f0, f1, f2, f3;
            unpack2(o2[i][0], f0, f1);
            unpack2(o2[i][1], f2, f3);
            float4 v;
            v.x = f0 * ri; v.y = f1 * ri; v.z = f2 * ri; v.w = f3 * ri;
            *(float4*)&outg[obase + (size_t)r * Dn] = v;
        }
    }
}

// ============================================================================
// Launch
// ============================================================================
extern "C" void kernel_launch(void* const* d_in, const int* in_sizes, int n_in,
                              void* d_out, int out_size)
{
    const float* q      = (const float*)d_in[0];
    const float* keys   = (const float*)d_in[1];
    const float* values = (const float*)d_in[2];
    const float* pk     = (const float*)d_in[3];
    const float* pv     = (const float*)d_in[4];
    float* out = (float*)d_out;

    cudaFuncSetAttribute(proj_mma_kernel,
                         cudaFuncAttributeMaxDynamicSharedMemorySize, PJ_SMEM);
    cudaFuncSetAttribute(attn_kernel,
                         cudaFuncAttributeMaxDynamicSharedMemorySize, SMEM2_BYTES);

    ptrans_kernel<<<dim3(Nn / 32, 2), 256>>>(pk, pv);
    proj_mma_kernel<<<dim3(8, Bsz, 2), 512, PJ_SMEM>>>(keys, values);
    attn_kernel<<<dim3(Nn / 128, Hn, Bsz), 256, SMEM2_BYTES>>>(q, out);
}

// round 5
// speedup vs baseline: 2.6520x; 1.9966x over previous
#include <cuda_runtime.h>
#include <cstdint>
#include <cstddef>

// Problem constants
#define Bsz 8
#define Hn  16
#define Nn  4096
#define DHn 64
#define Kn  128
#define Dn  1024

// Device scratch (no allocs allowed)
__device__ float    g_kp[Bsz * Kn * Dn];           // 4 MB projected keys
__device__ float    g_vp[Bsz * Kn * Dn];           // 4 MB projected values
__device__ uint32_t g_PTh[2 * Kn * (Nn / 2)];      // P^T hi bf16 pairs [w][k][n/2]
__device__ uint32_t g_PTl[2 * Kn * (Nn / 2)];      // P^T lo bf16 pairs

typedef unsigned long long u64;

// ---------------------------------------------------------------------------
// helpers
// ---------------------------------------------------------------------------
// pack two f32 -> bf16x2 (hi_elem -> upper 16 bits, lo_elem -> lower 16 bits)
__device__ __forceinline__ uint32_t cvt2bf(float hi_elem, float lo_elem) {
    uint32_t r;
    asm("cvt.rn.bf16x2.f32 %0, %1, %2;" : "=r"(r) : "f"(hi_elem), "f"(lo_elem));
    return r;
}
__device__ __forceinline__ float bflo_f(uint32_t p) { return __uint_as_float(p << 16); }
__device__ __forceinline__ float bfhi_f(uint32_t p) { return __uint_as_float(p & 0xffff0000u); }

// swizzles: XOR 16B-unit index bits with low row bits (row stride 128B / 256B)
#define SWZ128(x) ((x) ^ (((x) >> 3) & 0x70))
#define SWZ256(x) ((x) ^ (((x) >> 4) & 0x70))

#define LDSM4(r, a) \
    asm volatile("ldmatrix.sync.aligned.m8n8.x4.shared.b16 {%0,%1,%2,%3}, [%4];" \
        : "=r"((r)[0]), "=r"((r)[1]), "=r"((r)[2]), "=r"((r)[3]) : "r"(a))
#define LDSM4T(r, a) \
    asm volatile("ldmatrix.sync.aligned.m8n8.x4.trans.shared.b16 {%0,%1,%2,%3}, [%4];" \
        : "=r"((r)[0]), "=r"((r)[1]), "=r"((r)[2]), "=r"((r)[3]) : "r"(a))
#define MMA_BF16(c, a, b0v, b1v) \
    asm volatile("mma.sync.aligned.m16n8k16.row.col.f32.bf16.bf16.f32 " \
        "{%0,%1,%2,%3}, {%4,%5,%6,%7}, {%8,%9}, {%0,%1,%2,%3};" \
        : "+f"((c)[0]), "+f"((c)[1]), "+f"((c)[2]), "+f"((c)[3]) \
        : "r"((a)[0]), "r"((a)[1]), "r"((a)[2]), "r"((a)[3]), "r"(b0v), "r"(b1v))

__device__ __forceinline__ uint32_t smem_u32(const void* p) {
    uint32_t a;
    asm("{ .reg .u64 t; cvta.to.shared.u64 t, %1; cvt.u32.u64 %0, t; }" : "=r"(a) : "l"(p));
    return a;
}

// split a float4 (optionally scaled) into hi/lo bf16x2 pairs
__device__ __forceinline__ void split4(float4 v, float s, uint2& h, uint2& l) {
    v.x *= s; v.y *= s; v.z *= s; v.w *= s;
    uint32_t h01 = cvt2bf(v.y, v.x);
    uint32_t h23 = cvt2bf(v.w, v.z);
    float h0 = bflo_f(h01), h1 = bfhi_f(h01);
    float h2 = bflo_f(h23), h3 = bfhi_f(h23);
    uint32_t l01 = cvt2bf(v.y - h1, v.x - h0);
    uint32_t l23 = cvt2bf(v.w - h3, v.z - h2);
    h = make_uint2(h01, h23);
    l = make_uint2(l01, l23);
}

// ============================================================================
// Kernel 0: transpose P [4096 n][128 k] -> split-bf16 PT [w][128 k][4096 n]
// ============================================================================
__global__ void __launch_bounds__(256) ptrans_kernel(
    const float* __restrict__ pk, const float* __restrict__ pv)
{
    __shared__ float sT[128][33];
    const int t  = threadIdx.x;
    const int n0 = blockIdx.x * 32;
    const int w  = blockIdx.y;
    const float* __restrict__ P = w ? pv : pk;

    #pragma unroll
    for (int i = 0; i < 16; i++) {
        int idx = t + 256 * i;
        int r = idx >> 7, c = idx & 127;
        sT[c][r] = P[(size_t)(n0 + r) * Kn + c];
    }
    __syncthreads();

    uint32_t* __restrict__ oh = g_PTh + (size_t)w * Kn * (Nn / 2);
    uint32_t* __restrict__ ol = g_PTl + (size_t)w * Kn * (Nn / 2);
    #pragma unroll
    for (int i = 0; i < 8; i++) {
        int idx = t + 256 * i;
        int k = idx >> 4, pr = idx & 15;
        float x0 = sT[k][2 * pr], x1 = sT[k][2 * pr + 1];
        uint32_t h = cvt2bf(x1, x0);
        float h0 = bflo_f(h), h1 = bfhi_f(h);
        uint32_t l = cvt2bf(x1 - h1, x0 - h0);
        size_t o = (size_t)k * (Nn / 2) + (n0 >> 1) + pr;
        oh[o] = h;
        ol[o] = l;
    }
}

// ============================================================================
// Kernel 1: mma.sync bf16-split projection (unchanged from round 4; 148us)
// ============================================================================
#define PJ_AHI 0
#define PJ_ALO 16384
#define PJ_BHI 32768
#define PJ_BLO 49152
#define PJ_STAGE 65536
#define PJ_SMEM (2 * PJ_STAGE)

__global__ void __launch_bounds__(512, 1) proj_mma_kernel(
    const float* __restrict__ keys, const float* __restrict__ values)
{
    const int dt = blockIdx.x;
    const int b  = blockIdx.y;
    const int w  = blockIdx.z;

    const float* __restrict__ X = (w ? values : keys) + (size_t)b * Nn * Dn + dt * 128;
    const uint32_t* __restrict__ PTh = g_PTh + (size_t)w * Kn * (Nn / 2);
    const uint32_t* __restrict__ PTl = g_PTl + (size_t)w * Kn * (Nn / 2);
    float* __restrict__ Cg = (w ? g_vp : g_kp) + (size_t)b * Kn * Dn + dt * 128;

    extern __shared__ __align__(1024) unsigned char dsm[];
    const uint32_t sbase = smem_u32(dsm);

    const int tid  = threadIdx.x;
    const int wid  = tid >> 5, lane = tid & 31;
    const int warp_m = (wid >> 2) * 32;
    const int warp_d = (wid & 3) * 32;

    float acc[2][4][4];
    #pragma unroll
    for (int i = 0; i < 2; i++)
        #pragma unroll
        for (int j = 0; j < 4; j++)
            #pragma unroll
            for (int q = 0; q < 4; q++) acc[i][j][q] = 0.0f;

    uint4  pA[4];
    float4 pB[4];

    #pragma unroll
    for (int u = 0; u < 2; u++) {
        int idx = tid + 512 * u;
        int row = idx >> 3, c8 = idx & 7;
        size_t o = (size_t)row * (Nn / 2) + c8 * 4;
        pA[u]     = *(const uint4*)&PTh[o];
        pA[2 + u] = *(const uint4*)&PTl[o];
    }
    #pragma unroll
    for (int u = 0; u < 4; u++) {
        int idx = tid + 512 * u;
        int row = idx >> 5, c4 = idx & 31;
        pB[u] = *(const float4*)&X[(size_t)row * Dn + c4 * 4];
    }

    for (int c = 0; c < 64; ++c) {
        unsigned char* st = dsm + (c & 1) * PJ_STAGE;

        #pragma unroll
        for (int u = 0; u < 2; u++) {
            int idx = tid + 512 * u;
            int row = idx >> 3, c8 = idx & 7;
            uint32_t off = SWZ128((uint32_t)(row * 128 + c8 * 16));
            *(uint4*)(st + PJ_AHI + off) = pA[u];
            *(uint4*)(st + PJ_ALO + off) = pA[2 + u];
        }
        #pragma unroll
        for (int u = 0; u < 4; u++) {
            int idx = tid + 512 * u;
            int row = idx >> 5, c4 = idx & 31;
            uint2 hh, ll;
            split4(pB[u], 1.0f, hh, ll);
            uint32_t off = SWZ256((uint32_t)(row * 256 + c4 * 8));
            *(uint2*)(st + PJ_BHI + off) = hh;
            *(uint2*)(st + PJ_BLO + off) = ll;
        }
        __syncthreads();

        if (c < 63) {
            int nb = (c + 1) * 64;
            #pragma unroll
            for (int u = 0; u < 2; u++) {
                int idx = tid + 512 * u;
                int row = idx >> 3, c8 = idx & 7;
                size_t o = (size_t)row * (Nn / 2) + (nb >> 1) + c8 * 4;
                pA[u]     = *(const uint4*)&PTh[o];
                pA[2 + u] = *(const uint4*)&PTl[o];
            }
            #pragma unroll
            for (int u = 0; u < 4; u++) {
                int idx = tid + 512 * u;
                int row = idx >> 5, c4 = idx & 31;
                pB[u] = *(const float4*)&X[(size_t)(nb + row) * Dn + c4 * 4];
            }
        }

        const uint32_t sA = sbase + (c & 1) * PJ_STAGE;
        const uint32_t sB = sA + PJ_BHI;
        #pragma unroll
        for (int ks = 0; ks < 4; ks++) {
            uint32_t ah[2][4], al[2][4];
            #pragma unroll
            for (int mi = 0; mi < 2; mi++) {
                uint32_t off = SWZ128((uint32_t)((warp_m + mi * 16 + (lane & 15)) * 128
                                                 + ks * 32 + (lane >> 4) * 16));
                LDSM4(ah[mi], sA + PJ_AHI + off);
                LDSM4(al[mi], sA + PJ_ALO + off);
            }
            #pragma unroll
            for (int g2 = 0; g2 < 2; g2++) {
                uint32_t offb = SWZ256((uint32_t)((ks * 16 + (lane & 15)) * 256
                                                  + warp_d * 2 + g2 * 32 + (lane >> 4) * 16));
                uint32_t bh[4], bl[4];
                LDSM4T(bh, sB + offb);
                LDSM4T(bl, sB + (PJ_BLO - PJ_BHI) + offb);
                #pragma unroll
                for (int mi = 0; mi < 2; mi++) {
                    #pragma unroll
                    for (int jj = 0; jj < 2; jj++) {
                        float* cc = acc[mi][g2 * 2 + jj];
                        MMA_BF16(cc, ah[mi], bh[jj * 2], bh[jj * 2 + 1]);
                        MMA_BF16(cc, ah[mi], bl[jj * 2], bl[jj * 2 + 1]);
                        MMA_BF16(cc, al[mi], bh[jj * 2], bh[jj * 2 + 1]);
                    }
                }
            }
        }
        __syncthreads();
    }

    #pragma unroll
    for (int mi = 0; mi < 2; mi++) {
        #pragma unroll
        for (int j = 0; j < 4; j++) {
            int row = warp_m + mi * 16 + (lane >> 2);
            int col = warp_d + j * 8 + (lane & 3) * 2;
            *(float2*)&Cg[(size_t)row * Dn + col] =
                make_float2(acc[mi][j][0], acc[mi][j][1]);
            *(float2*)&Cg[(size_t)(row + 8) * Dn + col] =
                make_float2(acc[mi][j][2], acc[mi][j][3]);
        }
    }
}

// ============================================================================
// Kernel 2: tensor-core attention.  Per CTA: (b, h, 128-row n-tile).
// smem (bytes):
//   QHI 0, QLO 16K, KHI 32K, KLO 48K        (dead after GEMM1)
//   PHI 0, PLO 32K                           (reuse Q/K region)
//   VHI 64K, VLO 80K
//   SMAX 96K (128*2 fl), SSUM +1K           total 98K
// 8 warps. GEMM1: 4 m-groups x 2 k-halves. GEMM2: 4 m-groups x 2 dh-halves.
// ============================================================================
#define AT_QHI  0
#define AT_QLO  16384
#define AT_KHI  32768
#define AT_KLO  49152
#define AT_PHI  0
#define AT_PLO  32768
#define AT_VHI  65536
#define AT_VLO  81920
#define AT_SMAX 98304
#define AT_SSUM 99328
#define AT_SMEM 100352

__global__ void __launch_bounds__(256, 2) attn_mma_kernel(
    const float* __restrict__ qg, float* __restrict__ outg)
{
    const int nt = blockIdx.x;
    const int h  = blockIdx.y;
    const int b  = blockIdx.z;

    extern __shared__ __align__(1024) unsigned char smb[];
    const uint32_t sbase = smem_u32(smb);
    float* smax = (float*)(smb + AT_SMAX);
    float* ssum = (float*)(smb + AT_SSUM);

    const int tid  = threadIdx.x;
    const int wid  = tid >> 5, lane = tid & 31;
    const int g    = lane >> 2, tk = lane & 3;
    const int wm   = (wid >> 1) * 32;      // m-group (rows)
    const int kh   = wid & 1;              // k-half / dh-half selector

    // ---- load + split Q (x0.125), KK, VV into smem ----
    {
        const size_t qbase = ((size_t)b * Nn + (size_t)nt * 128) * Dn + h * 64;
        const size_t kbase = (size_t)b * Kn * Dn + h * 64;
        #pragma unroll
        for (int t = 0; t < 8; t++) {
            int idx = tid + 256 * t;
            int row = idx >> 4, c4 = idx & 15;         // row 0..127, dh = c4*4
            size_t go = (size_t)row * Dn + c4 * 4;
            uint32_t off = SWZ128((uint32_t)(row * 128 + c4 * 8));
            uint2 hh, ll;
            split4(*(const float4*)&qg[qbase + go], 0.125f, hh, ll);
            *(uint2*)(smb + AT_QHI + off) = hh;
            *(uint2*)(smb + AT_QLO + off) = ll;
            split4(*(const float4*)&g_kp[kbase + go], 1.0f, hh, ll);
            *(uint2*)(smb + AT_KHI + off) = hh;
            *(uint2*)(smb + AT_KLO + off) = ll;
            split4(*(const float4*)&g_vp[kbase + go], 1.0f, hh, ll);
            *(uint2*)(smb + AT_VHI + off) = hh;
            *(uint2*)(smb + AT_VLO + off) = ll;
        }
    }
    __syncthreads();

    // ---- GEMM1: dots[128n x 128k]; warp tile 32n x 64k; dots in registers ----
    float acc[2][8][4];
    #pragma unroll
    for (int i = 0; i < 2; i++)
        #pragma unroll
        for (int j = 0; j < 8; j++)
            #pragma unroll
            for (int q = 0; q < 4; q++) acc[i][j][q] = 0.0f;

    {
        const int wk = kh * 64;    // this warp's k-column base
        #pragma unroll
        for (int ks = 0; ks < 4; ks++) {
            uint32_t ah[2][4], al[2][4];
            #pragma unroll
            for (int mi = 0; mi < 2; mi++) {
                uint32_t off = SWZ128((uint32_t)((wm + mi * 16 + (lane & 15)) * 128
                                                 + ks * 32 + (lane >> 4) * 16));
                LDSM4(ah[mi], sbase + AT_QHI + off);
                LDSM4(al[mi], sbase + AT_QLO + off);
            }
            #pragma unroll
            for (int jj = 0; jj < 4; jj++) {
                uint32_t offb = SWZ128((uint32_t)((wk + jj * 16 + (lane & 15)) * 128
                                                  + ks * 32 + (lane >> 4) * 16));
                uint32_t bh[4], bl[4];
                LDSM4(bh, sbase + AT_KHI + offb);
                LDSM4(bl, sbase + AT_KLO + offb);
                // non-trans B pairing: tile(2jj)=(r0,r2), tile(2jj+1)=(r1,r3)
                #pragma unroll
                for (int mi = 0; mi < 2; mi++) {
                    float* c0 = acc[mi][jj * 2];
                    MMA_BF16(c0, ah[mi], bh[0], bh[2]);
                    MMA_BF16(c0, ah[mi], bl[0], bl[2]);
                    MMA_BF16(c0, al[mi], bh[0], bh[2]);
                    float* c1 = acc[mi][jj * 2 + 1];
                    MMA_BF16(c1, ah[mi], bh[1], bh[3]);
                    MMA_BF16(c1, ah[mi], bl[1], bl[3]);
                    MMA_BF16(c1, al[mi], bh[1], bh[3]);
                }
            }
        }
    }

    // ---- softmax part 1: row max (quad shuffle + cross-warp smem) ----
    #pragma unroll
    for (int mi = 0; mi < 2; mi++) {
        #pragma unroll
        for (int h2 = 0; h2 < 2; h2++) {
            float m = acc[mi][0][h2 * 2];
            #pragma unroll
            for (int j = 0; j < 8; j++)
                m = fmaxf(m, fmaxf(acc[mi][j][h2 * 2], acc[mi][j][h2 * 2 + 1]));
            m = fmaxf(m, __shfl_xor_sync(0xffffffffu, m, 1));
            m = fmaxf(m, __shfl_xor_sync(0xffffffffu, m, 2));
            if (tk == 0) smax[(wm + mi * 16 + g + h2 * 8) * 2 + kh] = m;
        }
    }
    __syncthreads();

    // ---- softmax part 2: exp, row sums, write split-bf16 P into smem ----
    #pragma unroll
    for (int mi = 0; mi < 2; mi++) {
        #pragma unroll
        for (int h2 = 0; h2 < 2; h2++) {
            int row = wm + mi * 16 + g + h2 * 8;
            float M = fmaxf(smax[row * 2], smax[row * 2 + 1]);
            float s = 0.0f;
            #pragma unroll
            for (int j = 0; j < 8; j++) {
                float x0 = __expf(acc[mi][j][h2 * 2]     - M);
                float x1 = __expf(acc[mi][j][h2 * 2 + 1] - M);
                s += x0 + x1;
                uint32_t hi = cvt2bf(x1, x0);
                float f0 = bflo_f(hi), f1 = bfhi_f(hi);
                uint32_t lo = cvt2bf(x1 - f1, x0 - f0);
                uint32_t off = SWZ256((uint32_t)(row * 256 + kh * 128 + j * 16 + tk * 4));
                *(uint32_t*)(smb + AT_PHI + off) = hi;
                *(uint32_t*)(smb + AT_PLO + off) = lo;
            }
            s += __shfl_xor_sync(0xffffffffu, s, 1);
            s += __shfl_xor_sync(0xffffffffu, s, 2);
            if (tk == 0) ssum[row * 2 + kh] = s;
        }
    }
    __syncthreads();

    // ---- GEMM2: out[128n x 64dh] = P . VV; warp tile 32n x 32dh, k=128 ----
    float o[2][4][4];
    #pragma unroll
    for (int i = 0; i < 2; i++)
        #pragma unroll
        for (int j = 0; j < 4; j++)
            #pragma unroll
            for (int q = 0; q < 4; q++) o[i][j][q] = 0.0f;

    {
        const int wdh = kh * 32;   // this warp's dh base
        #pragma unroll
        for (int ks = 0; ks < 8; ks++) {
            uint32_t ah[2][4], al[2][4];
            #pragma unroll
            for (int mi = 0; mi < 2; mi++) {
                uint32_t off = SWZ256((uint32_t)((wm + mi * 16 + (lane & 15)) * 256
                                                 + ks * 32 + (lane >> 4) * 16));
                LDSM4(ah[mi], sbase + AT_PHI + off);
                LDSM4(al[mi], sbase + AT_PLO + off);
            }
            #pragma unroll
            for (int g2 = 0; g2 < 2; g2++) {
                uint32_t offb = SWZ128((uint32_t)((ks * 16 + (lane & 15)) * 128
                                                  + wdh * 2 + g2 * 32 + (lane >> 4) * 16));
                uint32_t bh[4], bl[4];
                LDSM4T(bh, sbase + AT_VHI + offb);
                LDSM4T(bl, sbase + AT_VLO + offb);
                // trans B pairing: tile(g2*2)=(r0,r1), tile(g2*2+1)=(r2,r3)
                #pragma unroll
                for (int mi = 0; mi < 2; mi++) {
                    #pragma unroll
                    for (int jj = 0; jj < 2; jj++) {
                        float* cc = o[mi][g2 * 2 + jj];
                        MMA_BF16(cc, ah[mi], bh[jj * 2], bh[jj * 2 + 1]);
                        MMA_BF16(cc, ah[mi], bl[jj * 2], bl[jj * 2 + 1]);
                        MMA_BF16(cc, al[mi], bh[jj * 2], bh[jj * 2 + 1]);
                    }
                }
            }
        }
    }

    // ---- epilogue: normalize by 1/rowsum, store ----
    {
        const int wdh = kh * 32;
        const size_t obase = ((size_t)b * Nn + (size_t)nt * 128) * Dn + h * 64;
        #pragma unroll
        for (int mi = 0; mi < 2; mi++) {
            int r0 = wm + mi * 16 + g;
            int r1 = r0 + 8;
            float ri0 = 1.0f / (ssum[r0 * 2] + ssum[r0 * 2 + 1]);
            float ri1 = 1.0f / (ssum[r1 * 2] + ssum[r1 * 2 + 1]);
            #pragma unroll
            for (int j = 0; j < 4; j++) {
                int col = wdh + j * 8 + tk * 2;
                *(float2*)&outg[obase + (size_t)r0 * Dn + col] =
                    make_float2(o[mi][j][0] * ri0, o[mi][j][1] * ri0);
                *(float2*)&outg[obase + (size_t)r1 * Dn + col] =
                    make_float2(o[mi][j][2] * ri1, o[mi][j][3] * ri1);
            }
        }
    }
}

// ============================================================================
// Launch
// ============================================================================
extern "C" void kernel_launch(void* const* d_in, const int* in_sizes, int n_in,
                              void* d_out, int out_size)
{
    const float* q      = (const float*)d_in[0];
    const float* keys   = (const float*)d_in[1];
    const float* values = (const float*)d_in[2];
    const float* pk     = (const float*)d_in[3];
    const float* pv     = (const float*)d_in[4];
    float* out = (float*)d_out;

    cudaFuncSetAttribute(proj_mma_kernel,
                         cudaFuncAttributeMaxDynamicSharedMemorySize, PJ_SMEM);
    cudaFuncSetAttribute(attn_mma_kernel,
                         cudaFuncAttributeMaxDynamicSharedMemorySize, AT_SMEM);

    ptrans_kernel<<<dim3(Nn / 32, 2), 256>>>(pk, pv);
    proj_mma_kernel<<<dim3(8, Bsz, 2), 512, PJ_SMEM>>>(keys, values);
    attn_mma_kernel<<<dim3(Nn / 128, Hn, Bsz), 256, AT_SMEM>>>(q, out);
}